// round 14
// baseline (speedup 1.0000x reference)
#include <cuda_runtime.h>
#include <cstdint>

// Problem constants
#define B_    16
#define T_    60
#define N_    196
#define C_    512
#define SEGS_ 10
#define TOPK_ 6
#define TOPM_ 12
#define HEADS_ 4
#define HD_   128
#define CLIP_ 6      // T/SEGS
#define FRAMES_ 36   // CLIP*TOPK
#define SCALE_ 0.08838834764831845f  // 1/sqrt(128)

// Output layout (flattened tuple concat):
//   [0, 294912)              audio_top_k        (B, FRAMES, C)
//   [294912, 3833856)        visual_patch_top_m (B, FRAMES, TOPM, C)
//   [3833856, 7372800)       visual_patch_feat  (B, FRAMES*TOPM, C) == same data
#define OUT_AUDIO_ 0
#define OUT_TOPM_  (B_*FRAMES_*C_)                    // 294912
#define OUT_FEAT_  (OUT_TOPM_ + B_*FRAMES_*TOPM_*C_)  // 3833856

// Block-role layout (single fused kernel, blockDim = 128):
//   [0, 128)     K1: q projection (warp-per-output, 4 outputs/block)
//   [128, 144)   K2: qW (head, 128-col chunk); spins q_flags[idx]
//   [144, 340)   K3a: scores per patch n; spins qw_flags; LAST block runs K3b
//   [340, 916)   K4: audio copy (no dep), then spin pid_flags, patch broadcast
// 916 blocks, all co-resident (148 SMs x 8 blocks @ __launch_bounds__(128,8)).
#define NB_K1_     128
#define NB_K2_     16
#define NB_K3A_    N_
#define B0_K2_     (NB_K1_)                 // 128
#define B0_K3A_    (B0_K2_ + NB_K2_)        // 144
#define B0_K4_     (B0_K3A_ + NB_K3A_)      // 340
#define NB_K4_     (B_*FRAMES_)             // 576
#define NB_TOTAL_  (B0_K4_ + NB_K4_)        // 916

#define NQF_   16   // q_flags copies   (one per K2 block)
#define NQWF_  8    // qw_flags copies
#define NPF_   64   // pid_flags copies
#define FSTR_  32   // flag stride in ints (one flag per 128B line)

// Device scratch + sync state (no allocations allowed; reset each run)
__device__ float g_q[C_];
__device__ float g_qW[HEADS_*C_];
__device__ float g_scores[HEADS_][N_];
__device__ int   c_q    = 0;                  // K1 blocks done (128)
__device__ int   c_qw   = 0;                  // K2 blocks done (16)
__device__ int   c_sc   = 0;                  // K3a blocks done (196)
__device__ int   c_done = 0;                  // K4 blocks done (576)
__device__ int   q_flags [NQF_  * FSTR_];     // 0/1
__device__ int   qw_flags[NQWF_ * FSTR_];     // 0/1
__device__ int   pid_flags[NPF_ * FSTR_];     // 0 = not ready, else pid+1

// Spin until *p != 0. Volatile loads, distributed addresses, short sleep.
__device__ __forceinline__ int poll_flag(const int* p) {
    const volatile int* vp = (const volatile int*)p;
    int v = *vp;
    while (v == 0) { __nanosleep(64); v = *vp; }
    return v;
}

// Block-wide: wait for flag, then acquire (fence) so guarded data is visible.
__device__ __forceinline__ void spin_acquire(const int* p) {
    if (threadIdx.x == 0) {
        poll_flag(p);
        __threadfence();
    }
    __syncthreads();
}

__global__ void __launch_bounds__(128, 8)
fused_kernel(const float* __restrict__ audio,
             const float* __restrict__ patch,
             const float* __restrict__ qst,
             const int*   __restrict__ topk,
             const float* __restrict__ in_proj_w,
             const float* __restrict__ in_proj_b,
             float* __restrict__ out) {
    const int bid  = blockIdx.x;
    const int tid  = threadIdx.x;
    const int warp = tid >> 5;
    const int lane = tid & 31;

    if (bid < NB_K1_) {
        // ---- K1: q[j] = dot(qst[0,:], Wq[j,:]) + bq[j]; warp-per-output ----
        int j = bid * 4 + warp;  // 0..511
        const float4* wrow = (const float4*)(in_proj_w + (size_t)j * C_);
        const float4* qv   = (const float4*)qst;
        float acc = 0.f;
        #pragma unroll 4
        for (int i = lane; i < C_ / 4; i += 32) {
            float4 a = wrow[i];
            float4 b = qv[i];
            acc += a.x * b.x + a.y * b.y + a.z * b.z + a.w * b.w;
        }
        #pragma unroll
        for (int o = 16; o; o >>= 1) acc += __shfl_xor_sync(0xffffffffu, acc, o);
        if (lane == 0) g_q[j] = acc + in_proj_b[j];
        __syncthreads();
        if (tid == 0) {
            __threadfence();
            int old = atomicAdd(&c_q, 1);
            if (old == NB_K1_ - 1) {
                __threadfence();
                #pragma unroll
                for (int i = 0; i < NQF_; i++) q_flags[i * FSTR_] = 1;
            }
        }

    } else if (bid < B0_K3A_) {
        // ---- K2: qW[h,c] = sum_d q[h*HD+d] * Wk[h*HD+d, c] ----
        int idx = bid - B0_K2_;
        spin_acquire(&q_flags[idx * FSTR_]);
        int h = idx >> 2, chunk = idx & 3;
        int c = chunk * 128 + tid;
        __shared__ float sq[HD_];
        sq[tid] = g_q[h * HD_ + tid];
        __syncthreads();
        const float* Wk = in_proj_w + (size_t)C_ * C_;  // rows C..2C
        const float* base = Wk + (size_t)(h * HD_) * C_ + c;
        float acc = 0.f;
        #pragma unroll 32
        for (int d = 0; d < HD_; d++) acc += sq[d] * base[(size_t)d * C_];
        g_qW[h * C_ + c] = acc;
        __syncthreads();
        if (tid == 0) {
            __threadfence();
            int old = atomicAdd(&c_qw, 1);
            if (old == NB_K2_ - 1) {
                __threadfence();
                #pragma unroll
                for (int i = 0; i < NQWF_; i++) qw_flags[i * FSTR_] = 1;
            }
        }

    } else if (bid < B0_K4_) {
        // ---- K3a: scores[h,n] = SCALE * dot(patch[0,frame0,n,:], qW[h,:]) ----
        int n = bid - B0_K3A_;
        int frame0 = topk[0] * CLIP_;  // top_k_index_sort[0,0,0] * CLIP, b=0
        const float4* row =
            (const float4*)(patch + (((size_t)frame0 * N_) + n) * C_);
        // Preload this block's 2KB patch row before waiting (no dependency).
        float4 p0 = row[lane];
        float4 p1 = row[lane + 32];
        float4 p2 = row[lane + 64];
        float4 p3 = row[lane + 96];

        spin_acquire(&qw_flags[(n & (NQWF_ - 1)) * FSTR_]);

        const float4* wv = (const float4*)(g_qW + warp * C_);
        float4 w0 = wv[lane];
        float4 w1 = wv[lane + 32];
        float4 w2 = wv[lane + 64];
        float4 w3 = wv[lane + 96];
        float acc = p0.x*w0.x + p0.y*w0.y + p0.z*w0.z + p0.w*w0.w
                  + p1.x*w1.x + p1.y*w1.y + p1.z*w1.z + p1.w*w1.w
                  + p2.x*w2.x + p2.y*w2.y + p2.z*w2.z + p2.w*w2.w
                  + p3.x*w3.x + p3.y*w3.y + p3.z*w3.z + p3.w*w3.w;
        #pragma unroll
        for (int o = 16; o; o >>= 1) acc += __shfl_xor_sync(0xffffffffu, acc, o);
        if (lane == 0) g_scores[warp][n] = acc * SCALE_;
        __syncthreads();

        __shared__ int islast;
        if (tid == 0) {
            __threadfence();
            int old = atomicAdd(&c_sc, 1);
            islast = (old == NB_K3A_ - 1);
        }
        __syncthreads();

        if (islast) {
            // ---- K3b inline: softmax per head, mean, top-12 -> pid ----
            if (tid == 0) __threadfence();   // acquire other blocks' scores
            __syncthreads();
            __shared__ float w[HEADS_][N_];

            // warp h: softmax of head h, register-resident (7 vals/lane)
            float v[7];
            float m = -1e30f;
            #pragma unroll
            for (int j = 0; j < 7; j++) {
                int nn = lane + 32 * j;
                v[j] = (nn < N_) ? g_scores[warp][nn] : -1e30f;
                m = fmaxf(m, v[j]);
            }
            #pragma unroll
            for (int o = 16; o; o >>= 1)
                m = fmaxf(m, __shfl_xor_sync(0xffffffffu, m, o));
            float sum = 0.f;
            #pragma unroll
            for (int j = 0; j < 7; j++) {
                int nn = lane + 32 * j;
                float e = (nn < N_) ? expf(v[j] - m) : 0.f;
                v[j] = e;
                sum += e;
            }
            #pragma unroll
            for (int o = 16; o; o >>= 1)
                sum += __shfl_xor_sync(0xffffffffu, sum, o);
            float inv = 1.f / sum;
            #pragma unroll
            for (int j = 0; j < 7; j++) {
                int nn = lane + 32 * j;
                if (nn < N_) w[warp][nn] = v[j] * inv;
            }
            __syncthreads();

            if (warp == 0) {
                float pw[7];
                #pragma unroll
                for (int j = 0; j < 7; j++) {
                    int nn = lane + 32 * j;
                    pw[j] = (nn < N_)
                        ? 0.25f * (w[0][nn] + w[1][nn] + w[2][nn] + w[3][nn])
                        : -1e30f;
                }
                int pid = -1;
                #pragma unroll
                for (int it = 0; it < TOPM_; it++) {
                    float bv = -1e30f;
                    int bi = -1;
                    #pragma unroll
                    for (int j = 0; j < 7; j++) {
                        int nn = lane + 32 * j;
                        if (pw[j] > bv || (pw[j] == bv && nn > bi)) { bv = pw[j]; bi = nn; }
                    }
                    #pragma unroll
                    for (int o = 16; o; o >>= 1) {
                        float ov = __shfl_xor_sync(0xffffffffu, bv, o);
                        int   oi = __shfl_xor_sync(0xffffffffu, bi, o);
                        if (ov > bv || (ov == bv && oi > bi)) { bv = ov; bi = oi; }
                    }
                    if ((bi & 31) == lane) pw[bi >> 5] = -1e30f;  // retire winner
                    if (bi > pid) pid = bi;
                }
                // publish pid+1 to 64 distributed flags (flag IS the data).
                int val = pid + 1;
                volatile int* pf = (volatile int*)pid_flags;
                pf[(lane * 2)     * FSTR_] = val;
                pf[(lane * 2 + 1) * FSTR_] = val;
            }
        }

    } else {
        // ---- K4: audio copy (dep-free), then pid broadcast ----
        int bf = bid - B0_K4_;
        int b = bf / FRAMES_, f = bf % FRAMES_;
        int fk = f / CLIP_, cc = f % CLIP_;
        int seg = topk[b * TOPK_ + fk];     // top_k_index_sort[b,0,fk]
        int frame = seg * CLIP_ + cc;

        // audio: 512 floats = 128 float4, one per thread
        float4 a = ((const float4*)(audio + ((size_t)b * T_ + frame) * C_))[tid];
        ((float4*)(out + OUT_AUDIO_ + (size_t)bf * C_))[tid] = a;

        // wait for pid (value packed in flag; no fence needed — inputs only)
        __shared__ int spid;
        if (tid == 0) spid = poll_flag(&pid_flags[(bf & (NPF_ - 1)) * FSTR_]) - 1;
        __syncthreads();
        int pid = spid;

        float4 p = ((const float4*)(patch +
                     (((size_t)b * T_ + frame) * N_ + pid) * C_))[tid];

        float4* s1 = (float4*)(out + OUT_TOPM_ + (size_t)bf * TOPM_ * C_);
        float4* s2 = (float4*)(out + OUT_FEAT_ + (size_t)bf * TOPM_ * C_);
        #pragma unroll
        for (int mrow = 0; mrow < TOPM_; mrow++) {
            s1[mrow * (C_ / 4) + tid] = p;
            s2[mrow * (C_ / 4) + tid] = p;
        }

        // last K4 block resets all sync state for the next (graph) replay
        __syncthreads();
        if (tid == 0) {
            __threadfence();
            int old = atomicAdd(&c_done, 1);
            if (old == NB_K4_ - 1) {
                c_q = 0; c_qw = 0; c_sc = 0; c_done = 0;
                #pragma unroll
                for (int i = 0; i < NQF_; i++)  q_flags [i * FSTR_] = 0;
                #pragma unroll
                for (int i = 0; i < NQWF_; i++) qw_flags[i * FSTR_] = 0;
                for (int i = 0; i < NPF_; i++)  pid_flags[i * FSTR_] = 0;
                __threadfence();
            }
        }
    }
}

// ---------------------------------------------------------------------------
extern "C" void kernel_launch(void* const* d_in, const int* in_sizes, int n_in,
                              void* d_out, int out_size) {
    const float* audio_feat = (const float*)d_in[0];   // (B,T,C)
    const float* patch_feat = (const float*)d_in[1];   // (B,T,N,C)
    const float* qst_feat   = (const float*)d_in[2];   // (B,C)
    const int*   topk       = (const int*)d_in[3];     // (B,1,TOPK)
    const float* in_proj_w  = (const float*)d_in[4];   // (3C,C)
    const float* in_proj_b  = (const float*)d_in[5];   // (3C,)
    float* out = (float*)d_out;

    fused_kernel<<<NB_TOTAL_, 128>>>(audio_feat, patch_feat, qst_feat, topk,
                                     in_proj_w, in_proj_b, out);
}

// round 17
// speedup vs baseline: 1.4721x; 1.4721x over previous
#include <cuda_runtime.h>
#include <cstdint>

// Problem constants
#define B_    16
#define T_    60
#define N_    196
#define C_    512
#define SEGS_ 10
#define TOPK_ 6
#define TOPM_ 12
#define HEADS_ 4
#define HD_   128
#define CLIP_ 6      // T/SEGS
#define FRAMES_ 36   // CLIP*TOPK
#define SCALE_ 0.08838834764831845f  // 1/sqrt(128)

// Output layout (flattened tuple concat):
//   [0, 294912)              audio_top_k        (B, FRAMES, C)
//   [294912, 3833856)        visual_patch_top_m (B, FRAMES, TOPM, C)
//   [3833856, 7372800)       visual_patch_feat  (B, FRAMES*TOPM, C) == same data
#define OUT_AUDIO_ 0
#define OUT_TOPM_  (B_*FRAMES_*C_)                    // 294912
#define OUT_FEAT_  (OUT_TOPM_ + B_*FRAMES_*TOPM_*C_)  // 3833856

// Device scratch (no allocations allowed)
__device__ float g_q[C_];              // q projection of qst_feat[0]
__device__ float g_qW[HEADS_*C_];      // qW[h,c] = sum_d q[h*HD+d]*Wk[h*HD+d, c]
__device__ float g_scores[HEADS_][N_]; // pre-softmax scores (scaled)
__device__ int   g_pid;
__device__ int   c_sc = 0;             // k3 completion ticket (target N_)

// ---------------------------------------------------------------------------
// K1: q[j] = dot(qst_feat[0,:], Wq[j,:]) + bq[j].   One warp per output j.
// Launch: <<<64, 256>>>
// ---------------------------------------------------------------------------
__global__ void __launch_bounds__(256)
k1_qproj(const float* __restrict__ qst,
         const float* __restrict__ in_proj_w,
         const float* __restrict__ in_proj_b) {
    int gwarp = (blockIdx.x * blockDim.x + threadIdx.x) >> 5;  // 0..511
    int lane  = threadIdx.x & 31;
    const float4* wrow = (const float4*)(in_proj_w + (size_t)gwarp * C_);
    const float4* qv   = (const float4*)qst;
    float acc = 0.f;
    #pragma unroll 4
    for (int i = lane; i < C_ / 4; i += 32) {
        float4 a = wrow[i];
        float4 b = qv[i];
        acc += a.x * b.x + a.y * b.y + a.z * b.z + a.w * b.w;
    }
    #pragma unroll
    for (int o = 16; o; o >>= 1) acc += __shfl_xor_sync(0xffffffffu, acc, o);
    if (lane == 0) g_q[gwarp] = acc + in_proj_b[gwarp];
}

// ---------------------------------------------------------------------------
// K2: qW[h,c] = sum_{d<HD} q[h*HD+d] * Wk[h*HD+d, c]
// 16 blocks: (head, 128-col chunk). 128 threads = one column each.
// ---------------------------------------------------------------------------
__global__ void __launch_bounds__(128)
k2_qw(const float* __restrict__ in_proj_w) {
    int h     = blockIdx.x >> 2;          // 0..3
    int chunk = blockIdx.x & 3;           // 0..3
    int t     = threadIdx.x;              // 0..127
    int c     = chunk * 128 + t;
    __shared__ float sq[HD_];
    sq[t] = g_q[h * HD_ + t];
    __syncthreads();
    const float* Wk = in_proj_w + (size_t)C_ * C_;  // rows C..2C
    const float* base = Wk + (size_t)(h * HD_) * C_ + c;
    float acc = 0.f;
    #pragma unroll 16
    for (int d = 0; d < HD_; d++) {
        acc += sq[d] * base[(size_t)d * C_];
    }
    g_qW[h * C_ + c] = acc;
}

// ---------------------------------------------------------------------------
// K3: scores[h,n] = SCALE * dot(patch[0,frame0,n,:], qW[h,:])
// Grid of N_ blocks, 128 threads (4 warps = 4 heads per block).
// The LAST block to finish (atomic ticket) runs the softmax + mean + top-12
// selection inline and publishes g_pid — no separate tiny kernel launch.
// ---------------------------------------------------------------------------
__global__ void __launch_bounds__(128)
k3_scores_pid(const float* __restrict__ patch,
              const int* __restrict__ topk) {
    int n = blockIdx.x;
    int warp = threadIdx.x >> 5, lane = threadIdx.x & 31;
    int frame0 = topk[0] * CLIP_;  // top_k_index_sort[0,0,0] * CLIP, b=0

    const float4* row =
        (const float4*)(patch + (((size_t)frame0 * N_) + n) * C_);
    const float4* wv = (const float4*)(g_qW + warp * C_);
    float acc = 0.f;
    #pragma unroll 4
    for (int i = lane; i < C_ / 4; i += 32) {
        float4 p = row[i];
        float4 w = wv[i];
        acc += p.x * w.x + p.y * w.y + p.z * w.z + p.w * w.w;
    }
    #pragma unroll
    for (int o = 16; o; o >>= 1) acc += __shfl_xor_sync(0xffffffffu, acc, o);
    if (lane == 0) g_scores[warp][n] = acc * SCALE_;
    __syncthreads();

    __shared__ int islast;
    if (threadIdx.x == 0) {
        __threadfence();                      // release this block's scores
        int old = atomicAdd(&c_sc, 1);
        islast = (old == N_ - 1);
    }
    __syncthreads();
    if (!islast) return;

    // ---- inline K3b: softmax per head, mean, top-12 -> pid ----
    if (threadIdx.x == 0) __threadfence();    // acquire all blocks' scores
    __syncthreads();
    __shared__ float w[HEADS_][N_];

    // warp h: softmax of head h, register-resident (7 values per lane)
    float v[7];
    float m = -1e30f;
    #pragma unroll
    for (int j = 0; j < 7; j++) {
        int nn = lane + 32 * j;
        v[j] = (nn < N_) ? g_scores[warp][nn] : -1e30f;
        m = fmaxf(m, v[j]);
    }
    #pragma unroll
    for (int o = 16; o; o >>= 1) m = fmaxf(m, __shfl_xor_sync(0xffffffffu, m, o));
    float sum = 0.f;
    #pragma unroll
    for (int j = 0; j < 7; j++) {
        int nn = lane + 32 * j;
        float e = (nn < N_) ? expf(v[j] - m) : 0.f;
        v[j] = e;
        sum += e;
    }
    #pragma unroll
    for (int o = 16; o; o >>= 1) sum += __shfl_xor_sync(0xffffffffu, sum, o);
    float inv = 1.f / sum;
    #pragma unroll
    for (int j = 0; j < 7; j++) {
        int nn = lane + 32 * j;
        if (nn < N_) w[warp][nn] = v[j] * inv;
    }
    __syncthreads();

    if (warp == 0) {
        // pw in registers; 12 iterations of warp-argmax (tie -> larger index)
        float pw[7];
        #pragma unroll
        for (int j = 0; j < 7; j++) {
            int nn = lane + 32 * j;
            pw[j] = (nn < N_)
                ? 0.25f * (w[0][nn] + w[1][nn] + w[2][nn] + w[3][nn])
                : -1e30f;
        }
        int pid = -1;
        #pragma unroll
        for (int it = 0; it < TOPM_; it++) {
            float bv = -1e30f;
            int bi = -1;
            #pragma unroll
            for (int j = 0; j < 7; j++) {
                int nn = lane + 32 * j;
                if (pw[j] > bv || (pw[j] == bv && nn > bi)) { bv = pw[j]; bi = nn; }
            }
            #pragma unroll
            for (int o = 16; o; o >>= 1) {
                float ov = __shfl_xor_sync(0xffffffffu, bv, o);
                int   oi = __shfl_xor_sync(0xffffffffu, bi, o);
                if (ov > bv || (ov == bv && oi > bi)) { bv = ov; bi = oi; }
            }
            if ((bi & 31) == lane) pw[bi >> 5] = -1e30f;  // retire winner
            if (bi > pid) pid = bi;
        }
        if (lane == 0) {
            g_pid = pid;
            c_sc = 0;   // reset ticket for next graph replay (kernel boundary
                        // orders this before the next k3 launch)
        }
    }
}

// ---------------------------------------------------------------------------
// K4: writes all three outputs. 4 blocks per (b,f): block sub handles 3 TOPM
// rows of both replica outputs; sub==0 also writes the audio row.
// Launch: <<<576*4, 128>>>
// ---------------------------------------------------------------------------
__global__ void __launch_bounds__(128)
k4_out(const float* __restrict__ audio,
       const float* __restrict__ patch,
       const int* __restrict__ topk,
       float* __restrict__ out) {
    int bx = blockIdx.x;
    int bf = bx >> 2, sub = bx & 3;
    int b = bf / FRAMES_, f = bf % FRAMES_;
    int fk = f / CLIP_, cc = f % CLIP_;
    int seg = topk[b * TOPK_ + fk];   // top_k_index_sort[b,0,fk]
    int frame = seg * CLIP_ + cc;
    int t = threadIdx.x;
    int pid = g_pid;

    float4 p = ((const float4*)(patch +
                 (((size_t)b * T_ + frame) * N_ + pid) * C_))[t];

    if (sub == 0) {
        float4 a = ((const float4*)(audio + ((size_t)b * T_ + frame) * C_))[t];
        ((float4*)(out + OUT_AUDIO_ + (size_t)bf * C_))[t] = a;
    }

    float4* s1 = (float4*)(out + OUT_TOPM_ + (size_t)bf * TOPM_ * C_);
    float4* s2 = (float4*)(out + OUT_FEAT_ + (size_t)bf * TOPM_ * C_);
    #pragma unroll
    for (int mm = 0; mm < 3; mm++) {
        int mrow = sub * 3 + mm;
        s1[mrow * (C_ / 4) + t] = p;
        s2[mrow * (C_ / 4) + t] = p;
    }
}

// ---------------------------------------------------------------------------
extern "C" void kernel_launch(void* const* d_in, const int* in_sizes, int n_in,
                              void* d_out, int out_size) {
    const float* audio_feat = (const float*)d_in[0];   // (B,T,C)
    const float* patch_feat = (const float*)d_in[1];   // (B,T,N,C)
    const float* qst_feat   = (const float*)d_in[2];   // (B,C)
    const int*   topk       = (const int*)d_in[3];     // (B,1,TOPK)
    const float* in_proj_w  = (const float*)d_in[4];   // (3C,C)
    const float* in_proj_b  = (const float*)d_in[5];   // (3C,)
    float* out = (float*)d_out;

    k1_qproj<<<64, 256>>>(qst_feat, in_proj_w, in_proj_b);
    k2_qw<<<16, 128>>>(in_proj_w);
    k3_scores_pid<<<N_, 128>>>(patch_feat, topk);
    k4_out<<<B_ * FRAMES_ * 4, 128>>>(audio_feat, patch_feat, topk, out);
}